// round 10
// baseline (speedup 1.0000x reference)
#include <cuda_runtime.h>
#include <cuda_fp16.h>
#include <cuda_bf16.h>

// Problem constants
#define N_NODES   100000
#define N_EDGES   1600000
#define DIM       128
#define N_GRAPHS  1024
#define SCAN_BLOCKS 98          // ceil(100000/1024)
#define EDGE_VEC  (N_EDGES / 4) // 400000 int4 packets

// ---------------- scratch (__device__ globals: allocation-free) ----------------
__device__ unsigned g_bfA[(size_t)N_NODES * DIM / 2]; // 25.6 MB bf16x2: x16 / h1
__device__ unsigned g_bfB[(size_t)N_NODES * DIM / 2]; // 25.6 MB bf16x2: agg out
__device__ unsigned g_W1t[DIM * DIM / 2];             // W1^T in bf16: Wt[n][k]
__device__ int2     g_edge[N_EDGES];                  // (src, dinv[src] bits)
__device__ int      g_cnt[N_NODES];
__device__ float    g_dinv[N_NODES];
__device__ int      g_rowptr[N_NODES + 1];
__device__ int      g_cursor[N_NODES];
__device__ unsigned long long g_scan_pack[SCAN_BLOCKS]; // (flag<<32)|value

// bf16x2 (packed u32) -> two fp32: pure ALU (SHF/LOP3)
__device__ __forceinline__ float2 bf2f(unsigned u) {
    float2 r;
    r.x = __uint_as_float(u << 16);
    r.y = __uint_as_float(u & 0xFFFF0000u);
    return r;
}
// two fp32 -> packed bf16x2 (F2FP, fixed-lat pipe)
__device__ __forceinline__ unsigned f2bf(float a, float b) {
    __nv_bfloat162 h = __floats2bfloat162_rn(a, b);
    return *reinterpret_cast<unsigned*>(&h);
}

__device__ __forceinline__ int wsum32(int v) {
    #pragma unroll
    for (int o = 16; o > 0; o >>= 1) v += __shfl_xor_sync(0xffffffffu, v, o);
    return v;
}

// ---------------- fused prep: tobf16(x) | W1 transpose->bf16 | zero cnt/flags --
#define PREP_CONV_BLOCKS 1280
#define PREP_W_BLOCKS    32
#define PREP_Z_BLOCKS    98
__global__ void prep_kernel(const float* __restrict__ x, const float* __restrict__ W1) {
    int b = blockIdx.x;
    int tid = threadIdx.x;
    if (b < PREP_CONV_BLOCKS) {
        const int total = N_NODES * DIM / 4;
        int stride = PREP_CONV_BLOCKS * 256;
        for (int j = b * 256 + tid; j < total; j += stride) {
            float4 v = reinterpret_cast<const float4*>(x)[j];
            uint2 st;
            st.x = f2bf(v.x, v.y);
            st.y = f2bf(v.z, v.w);
            reinterpret_cast<uint2*>(g_bfA)[j] = st;
        }
    } else if (b < PREP_CONV_BLOCKS + PREP_W_BLOCKS) {
        int i = (b - PREP_CONV_BLOCKS) * 256 + tid;   // 0..8191
        int n = i >> 6;
        int k2 = (i & 63) * 2;
        float a = W1[(size_t)k2 * DIM + n];
        float c = W1[(size_t)(k2 + 1) * DIM + n];
        g_W1t[i] = f2bf(a, c);
    } else {
        int base = (b - PREP_CONV_BLOCKS - PREP_W_BLOCKS) * 256 + tid;
        int stride = PREP_Z_BLOCKS * 256;
        for (int j = base; j < N_NODES; j += stride) g_cnt[j] = 0;
        if (base < SCAN_BLOCKS) g_scan_pack[base] = 0ULL;
    }
}

// ---------------- degree histogram over dst (vectorized, 4 edges/thread) -----
__global__ void hist_kernel(const int4* __restrict__ dst4) {
    int i = blockIdx.x * blockDim.x + threadIdx.x;
    if (i < EDGE_VEC) {
        int4 d = dst4[i];
        atomicAdd(&g_cnt[d.x], 1);
        atomicAdd(&g_cnt[d.y], 1);
        atomicAdd(&g_cnt[d.z], 1);
        atomicAdd(&g_cnt[d.w], 1);
    }
}

// ---------------- single-pass scan: decoupled lookback + dinv + cursor -------
__global__ void scan_kernel() {
    __shared__ int warp_sums[32];
    __shared__ int s_prefix;
    int tid = threadIdx.x, lane = tid & 31, wid = tid >> 5;
    int b = blockIdx.x;
    int i = b * 1024 + tid;
    int v = (i < N_NODES) ? g_cnt[i] : 0;
    if (i < N_NODES) g_dinv[i] = rsqrtf((float)(v + 1));

    int x = v;
    #pragma unroll
    for (int o = 1; o < 32; o <<= 1) {
        int t = __shfl_up_sync(0xffffffffu, x, o);
        if (lane >= o) x += t;
    }
    if (lane == 31) warp_sums[wid] = x;
    __syncthreads();
    if (wid == 0) {
        int s = warp_sums[lane];
        #pragma unroll
        for (int o = 1; o < 32; o <<= 1) {
            int t = __shfl_up_sync(0xffffffffu, s, o);
            if (lane >= o) s += t;
        }
        warp_sums[lane] = s;
    }
    __syncthreads();
    int excl = (wid > 0 ? warp_sums[wid - 1] : 0) + x - v;
    int total = warp_sums[31];

    if (tid == 0) {
        unsigned long long p = (b == 0)
            ? ((2ULL << 32) | (unsigned)total)
            : ((1ULL << 32) | (unsigned)total);
        atomicExch(&g_scan_pack[b], p);
    }

    if (wid == 0) {
        int prefix = 0;
        if (b > 0) {
            int offset = 0;
            bool done = false;
            while (!done) {
                int my = b - 1 - offset - lane;
                int f = 2, val = 0;
                if (my >= 0) {
                    unsigned long long pv;
                    do {
                        pv = *((volatile unsigned long long*)&g_scan_pack[my]);
                        f = (int)(pv >> 32);
                    } while (f == 0);
                    val = (int)(pv & 0xffffffffULL);
                }
                unsigned m = __ballot_sync(0xffffffffu, f == 2);
                if (m == 0) {
                    prefix += wsum32(val);
                    offset += 32;
                } else {
                    int first = __ffs(m) - 1;
                    int c = (lane <= first) ? val : 0;
                    prefix += wsum32(c);
                    done = true;
                }
            }
        }
        if (lane == 0) {
            s_prefix = prefix;
            atomicExch(&g_scan_pack[b], (2ULL << 32) | (unsigned)(prefix + total));
        }
    }
    __syncthreads();
    int prefix = s_prefix;
    if (i < N_NODES) {
        int r = excl + prefix;
        g_rowptr[i] = r;
        g_cursor[i] = r;
    }
    if (b == 0 && tid == 0) g_rowptr[N_NODES] = N_EDGES;
}

// ---------------- counting-sort fill (vectorized, 4 independent chains) ------
__global__ void fill_kernel(const int4* __restrict__ src4, const int4* __restrict__ dst4) {
    int i = blockIdx.x * blockDim.x + threadIdx.x;
    if (i < EDGE_VEC) {
        int4 s = src4[i];
        int4 d = dst4[i];
        // issue all four dinv gathers + four cursor atomics independently
        float w0 = g_dinv[s.x];
        float w1 = g_dinv[s.y];
        float w2 = g_dinv[s.z];
        float w3 = g_dinv[s.w];
        int p0 = atomicAdd(&g_cursor[d.x], 1);
        int p1 = atomicAdd(&g_cursor[d.y], 1);
        int p2 = atomicAdd(&g_cursor[d.z], 1);
        int p3 = atomicAdd(&g_cursor[d.w], 1);
        g_edge[p0] = make_int2(s.x, __float_as_int(w0));
        g_edge[p1] = make_int2(s.y, __float_as_int(w1));
        g_edge[p2] = make_int2(s.z, __float_as_int(w2));
        g_edge[p3] = make_int2(s.w, __float_as_int(w3));
    }
}

// ---------------- aggregation (bf16 gather, fp32 accumulate, bf16 out) ------
__global__ void agg_kernel_bf(const unsigned* __restrict__ feat, unsigned* __restrict__ out) {
    int gtid = blockIdx.x * blockDim.x + threadIdx.x;
    int node = gtid >> 5;
    int lane = gtid & 31;
    if (node >= N_NODES) return;

    float di = g_dinv[node];
    uint2 sv = reinterpret_cast<const uint2*>(feat + (size_t)node * (DIM / 2))[lane];
    float2 s0 = bf2f(sv.x), s1 = bf2f(sv.y);
    float wsl = di * di;
    float4 acc = make_float4(wsl * s0.x, wsl * s0.y, wsl * s1.x, wsl * s1.y);

    int e0 = g_rowptr[node];
    int e1 = g_rowptr[node + 1];
    for (int eb = e0; eb < e1; eb += 32) {
        int nb = min(32, e1 - eb);
        int2 ew = make_int2(0, 0);
        float wown = 0.0f;
        if (lane < nb) {
            ew = g_edge[eb + lane];
            wown = di * __int_as_float(ew.y);
        }
        for (int j = 0; j < nb; ++j) {
            int sj   = __shfl_sync(0xffffffffu, ew.x, j);
            float wj = __shfl_sync(0xffffffffu, wown, j);
            uint2 d = reinterpret_cast<const uint2*>(feat + (size_t)sj * (DIM / 2))[lane];
            float2 f0 = bf2f(d.x), f1 = bf2f(d.y);
            acc.x += wj * f0.x; acc.y += wj * f0.y;
            acc.z += wj * f1.x; acc.w += wj * f1.y;
        }
    }
    uint2 st;
    st.x = f2bf(acc.x, acc.y);
    st.y = f2bf(acc.z, acc.w);
    reinterpret_cast<uint2*>(out + (size_t)node * (DIM / 2))[lane] = st;
}

// ---------------- tensor-core GEMM: C = relu(A @ W1 + b1), bf16 I/O ----------
#define LDP 72
__global__ void gemm_mma_bf(const unsigned* __restrict__ A,
                            const float* __restrict__ bias,
                            unsigned* __restrict__ C, int M) {
    __shared__ __nv_bfloat16 As[128][LDP];
    __shared__ __nv_bfloat16 Ws[128][LDP];
    __shared__ float bs[DIM];

    int tid = threadIdx.x;
    int wid = tid >> 5, lane = tid & 31;
    int g = lane >> 2, t = lane & 3;
    int row0 = blockIdx.x * 128;
    int wr = wid * 16;

    if (tid < DIM) bs[tid] = bias[tid];

    float acc[16][4];
    #pragma unroll
    for (int nt = 0; nt < 16; ++nt)
        #pragma unroll
        for (int j = 0; j < 4; ++j) acc[nt][j] = 0.0f;

    const unsigned* Wt = g_W1t;

    #pragma unroll
    for (int kc = 0; kc < DIM; kc += 64) {
        #pragma unroll
        for (int i = 0; i < 4; ++i) {
            int id = i * 256 + tid;
            int r = id >> 3, p = id & 7;
            int grow = min(row0 + r, M - 1);
            uint4 v = *reinterpret_cast<const uint4*>(
                A + (size_t)grow * (DIM / 2) + kc / 2 + p * 4);
            *reinterpret_cast<uint4*>(&As[r][p * 8]) = v;
        }
        #pragma unroll
        for (int i = 0; i < 4; ++i) {
            int id = i * 256 + tid;
            int n = id >> 3, p = id & 7;
            uint4 v = *reinterpret_cast<const uint4*>(
                Wt + (size_t)n * (DIM / 2) + kc / 2 + p * 4);
            *reinterpret_cast<uint4*>(&Ws[n][p * 8]) = v;
        }
        __syncthreads();

        #pragma unroll
        for (int ks = 0; ks < 64; ks += 16) {
            unsigned a0 = *reinterpret_cast<const unsigned*>(&As[wr + g][ks + 2 * t]);
            unsigned a1 = *reinterpret_cast<const unsigned*>(&As[wr + g + 8][ks + 2 * t]);
            unsigned a2 = *reinterpret_cast<const unsigned*>(&As[wr + g][ks + 2 * t + 8]);
            unsigned a3 = *reinterpret_cast<const unsigned*>(&As[wr + g + 8][ks + 2 * t + 8]);
            #pragma unroll
            for (int nt = 0; nt < 16; ++nt) {
                unsigned b0 = *reinterpret_cast<const unsigned*>(&Ws[nt * 8 + g][ks + 2 * t]);
                unsigned b1 = *reinterpret_cast<const unsigned*>(&Ws[nt * 8 + g][ks + 2 * t + 8]);
                asm volatile(
                    "mma.sync.aligned.m16n8k16.row.col.f32.bf16.bf16.f32 "
                    "{%0,%1,%2,%3}, {%4,%5,%6,%7}, {%8,%9}, {%0,%1,%2,%3};\n"
                    : "+f"(acc[nt][0]), "+f"(acc[nt][1]), "+f"(acc[nt][2]), "+f"(acc[nt][3])
                    : "r"(a0), "r"(a1), "r"(a2), "r"(a3), "r"(b0), "r"(b1));
            }
        }
        __syncthreads();
    }

    int rA = row0 + wr + g;
    int rB = rA + 8;
    #pragma unroll
    for (int nt = 0; nt < 16; ++nt) {
        int col = nt * 8 + 2 * t;
        float bx = bs[col], by = bs[col + 1];
        if (rA < M) {
            float ox = fmaxf(acc[nt][0] + bx, 0.0f);
            float oy = fmaxf(acc[nt][1] + by, 0.0f);
            C[(size_t)rA * (DIM / 2) + col / 2] = f2bf(ox, oy);
        }
        if (rB < M) {
            float ox = fmaxf(acc[nt][2] + bx, 0.0f);
            float oy = fmaxf(acc[nt][3] + by, 0.0f);
            C[(size_t)rB * (DIM / 2) + col / 2] = f2bf(ox, oy);
        }
    }
}

// ---------------- fused mean-pool (sorted batch, bf16 in) + W2 GEMM + b2 -----
__global__ void pool_gemm_kernel(const uint2* __restrict__ feat2,
                                 const int* __restrict__ batch,
                                 const float* __restrict__ W2,
                                 const float* __restrict__ b2,
                                 float* __restrict__ out) {
    __shared__ float4 sa[4][32];
    __shared__ float p[DIM];
    int g = blockIdx.x;
    int tid = threadIdx.x;
    int q = tid >> 5, l = tid & 31;

    int lo = 0, hi = N_NODES;
    while (lo < hi) { int m = (lo + hi) >> 1; if (batch[m] < g) lo = m + 1; else hi = m; }
    int start = lo;
    hi = N_NODES;
    while (lo < hi) { int m = (lo + hi) >> 1; if (batch[m] < g + 1) lo = m + 1; else hi = m; }
    int end = lo;

    float4 acc = make_float4(0.f, 0.f, 0.f, 0.f);
    for (int n = start + q; n < end; n += 4) {
        uint2 d = feat2[(size_t)n * (DIM / 4) + l];
        float2 f0 = bf2f(d.x), f1 = bf2f(d.y);
        acc.x += f0.x; acc.y += f0.y; acc.z += f1.x; acc.w += f1.y;
    }
    sa[q][l] = acc;
    __syncthreads();
    if (q == 0) {
        float4 s = sa[0][l];
        #pragma unroll
        for (int r = 1; r < 4; ++r) {
            float4 v = sa[r][l];
            s.x += v.x; s.y += v.y; s.z += v.z; s.w += v.w;
        }
        float cnt = fmaxf((float)(end - start), 1.0f);
        p[l * 4 + 0] = s.x / cnt;
        p[l * 4 + 1] = s.y / cnt;
        p[l * 4 + 2] = s.z / cnt;
        p[l * 4 + 3] = s.w / cnt;
    }
    __syncthreads();

    int j = tid;
    float o = b2[j];
    #pragma unroll 8
    for (int k = 0; k < DIM; ++k)
        o += p[k] * W2[k * DIM + j];
    out[g * DIM + j] = o;
}

// ---------------- launch ----------------
extern "C" void kernel_launch(void* const* d_in, const int* in_sizes, int n_in,
                              void* d_out, int out_size) {
    const float* x     = (const float*)d_in[0];
    const int*   ei    = (const int*)d_in[1];
    const int*   batch = (const int*)d_in[2];
    const float* W1    = (const float*)d_in[3];
    const float* b1    = (const float*)d_in[4];
    const float* W2    = (const float*)d_in[5];
    const float* b2    = (const float*)d_in[6];
    float* out = (float*)d_out;

    const int4* src4 = (const int4*)ei;               // edge_index[0]
    const int4* dst4 = (const int4*)(ei + N_EDGES);   // edge_index[1]

    unsigned* bfA; cudaGetSymbolAddress((void**)&bfA, g_bfA);
    unsigned* bfB; cudaGetSymbolAddress((void**)&bfB, g_bfB);

    prep_kernel<<<PREP_CONV_BLOCKS + PREP_W_BLOCKS + PREP_Z_BLOCKS, 256>>>(x, W1);
    hist_kernel<<<(EDGE_VEC + 255) / 256, 256>>>(dst4);
    scan_kernel<<<SCAN_BLOCKS, 1024>>>();
    fill_kernel<<<(EDGE_VEC + 255) / 256, 256>>>(src4, dst4);

    int agg_blocks = (N_NODES * 32 + 255) / 256;
    // layer 1: agg(x_bf16) -> bfB; h1 = relu(bfB @ W1 + b1) -> bfA  (tensor cores)
    agg_kernel_bf<<<agg_blocks, 256>>>(bfA, bfB);
    gemm_mma_bf<<<(N_NODES + 127) / 128, 256>>>(bfB, b1, bfA, N_NODES);

    // layer 2: agg(h1) -> bfB (bf16); W2 deferred past pooling
    agg_kernel_bf<<<agg_blocks, 256>>>(bfA, bfB);

    // fused mean-pool + W2 GEMM + b2
    pool_gemm_kernel<<<N_GRAPHS, DIM>>>(
        reinterpret_cast<const uint2*>(bfB), batch, W2, b2, out);
}

// round 12
// speedup vs baseline: 1.0974x; 1.0974x over previous
#include <cuda_runtime.h>
#include <cuda_fp16.h>
#include <cuda_bf16.h>

// Problem constants
#define N_NODES   100000
#define N_EDGES   1600000
#define DIM       128
#define N_GRAPHS  1024
#define SCAN_BLOCKS 98          // ceil(100000/1024)
#define EDGE_VEC  (N_EDGES / 4) // 400000 int4 packets

// ---------------- scratch (__device__ globals: allocation-free) ----------------
__device__ unsigned g_bfA[(size_t)N_NODES * DIM / 2]; // 25.6 MB bf16x2: y0 / y1
__device__ unsigned g_bfB[(size_t)N_NODES * DIM / 2]; // 25.6 MB bf16x2: agg out
__device__ unsigned g_W1t[DIM * DIM / 2];             // W1^T in bf16: Wt[n][k]
__device__ int      g_srcsorted[N_EDGES];             // 6.4 MB: src per CSR slot
__device__ int      g_rank[N_EDGES];                  // 6.4 MB: edge rank in dst bucket
__device__ int      g_cnt[N_NODES];
__device__ float    g_dinv[N_NODES];
__device__ int      g_rowptr[N_NODES + 1];
__device__ unsigned long long g_scan_pack[SCAN_BLOCKS]; // (flag<<32)|value

// bf16x2 (packed u32) -> two fp32: pure ALU (SHF/LOP3)
__device__ __forceinline__ float2 bf2f(unsigned u) {
    float2 r;
    r.x = __uint_as_float(u << 16);
    r.y = __uint_as_float(u & 0xFFFF0000u);
    return r;
}
// two fp32 -> packed bf16x2 (F2FP, fixed-lat pipe)
__device__ __forceinline__ unsigned f2bf(float a, float b) {
    __nv_bfloat162 h = __floats2bfloat162_rn(a, b);
    return *reinterpret_cast<unsigned*>(&h);
}

__device__ __forceinline__ int wsum32(int v) {
    #pragma unroll
    for (int o = 16; o > 0; o >>= 1) v += __shfl_xor_sync(0xffffffffu, v, o);
    return v;
}

// ---------------- prep: W1 transpose->bf16 | zero cnt + scan flags ----------
#define PREP_W_BLOCKS 32
#define PREP_Z_BLOCKS 98
__global__ void prep_kernel(const float* __restrict__ W1) {
    int b = blockIdx.x;
    int tid = threadIdx.x;
    if (b < PREP_W_BLOCKS) {
        int i = b * 256 + tid;          // 0..8191
        int n = i >> 6;
        int k2 = (i & 63) * 2;
        float a = W1[(size_t)k2 * DIM + n];
        float c = W1[(size_t)(k2 + 1) * DIM + n];
        g_W1t[i] = f2bf(a, c);
    } else {
        int base = (b - PREP_W_BLOCKS) * 256 + tid;
        int stride = PREP_Z_BLOCKS * 256;
        for (int j = base; j < N_NODES; j += stride) g_cnt[j] = 0;
        if (base < SCAN_BLOCKS) g_scan_pack[base] = 0ULL;
    }
}

// ---------------- histogram + rank capture (counting-sort phase 1) -----------
__global__ void hist_kernel(const int4* __restrict__ dst4) {
    int i = blockIdx.x * blockDim.x + threadIdx.x;
    if (i < EDGE_VEC) {
        int4 d = dst4[i];
        int4 r;
        r.x = atomicAdd(&g_cnt[d.x], 1);
        r.y = atomicAdd(&g_cnt[d.y], 1);
        r.z = atomicAdd(&g_cnt[d.z], 1);
        r.w = atomicAdd(&g_cnt[d.w], 1);
        reinterpret_cast<int4*>(g_rank)[i] = r;
    }
}

// ---------------- single-pass scan: decoupled lookback + dinv ----------------
__global__ void scan_kernel() {
    __shared__ int warp_sums[32];
    __shared__ int s_prefix;
    int tid = threadIdx.x, lane = tid & 31, wid = tid >> 5;
    int b = blockIdx.x;
    int i = b * 1024 + tid;
    int v = (i < N_NODES) ? g_cnt[i] : 0;
    if (i < N_NODES) g_dinv[i] = rsqrtf((float)(v + 1));

    int x = v;
    #pragma unroll
    for (int o = 1; o < 32; o <<= 1) {
        int t = __shfl_up_sync(0xffffffffu, x, o);
        if (lane >= o) x += t;
    }
    if (lane == 31) warp_sums[wid] = x;
    __syncthreads();
    if (wid == 0) {
        int s = warp_sums[lane];
        #pragma unroll
        for (int o = 1; o < 32; o <<= 1) {
            int t = __shfl_up_sync(0xffffffffu, s, o);
            if (lane >= o) s += t;
        }
        warp_sums[lane] = s;
    }
    __syncthreads();
    int excl = (wid > 0 ? warp_sums[wid - 1] : 0) + x - v;
    int total = warp_sums[31];

    if (tid == 0) {
        unsigned long long p = (b == 0)
            ? ((2ULL << 32) | (unsigned)total)
            : ((1ULL << 32) | (unsigned)total);
        atomicExch(&g_scan_pack[b], p);
    }

    if (wid == 0) {
        int prefix = 0;
        if (b > 0) {
            int offset = 0;
            bool done = false;
            while (!done) {
                int my = b - 1 - offset - lane;
                int f = 2, val = 0;
                if (my >= 0) {
                    unsigned long long pv;
                    do {
                        pv = *((volatile unsigned long long*)&g_scan_pack[my]);
                        f = (int)(pv >> 32);
                    } while (f == 0);
                    val = (int)(pv & 0xffffffffULL);
                }
                unsigned m = __ballot_sync(0xffffffffu, f == 2);
                if (m == 0) {
                    prefix += wsum32(val);
                    offset += 32;
                } else {
                    int first = __ffs(m) - 1;
                    int c = (lane <= first) ? val : 0;
                    prefix += wsum32(c);
                    done = true;
                }
            }
        }
        if (lane == 0) {
            s_prefix = prefix;
            atomicExch(&g_scan_pack[b], (2ULL << 32) | (unsigned)(prefix + total));
        }
    }
    __syncthreads();
    int prefix = s_prefix;
    if (i < N_NODES) g_rowptr[i] = excl + prefix;
    if (b == 0 && tid == 0) g_rowptr[N_NODES] = N_EDGES;
}

// ---------------- y0 = dinv ⊙ x, packed bf16 (after scan) -------------------
__global__ void convy_kernel(const float* __restrict__ x) {
    int i = blockIdx.x * blockDim.x + threadIdx.x;
    const int total = N_NODES * DIM / 4;     // float4 packets (32 per row)
    int stride = gridDim.x * blockDim.x;
    for (int j = i; j < total; j += stride) {
        int row = j >> 5;
        float di = __ldg(&g_dinv[row]);
        float4 v = reinterpret_cast<const float4*>(x)[j];
        uint2 st;
        st.x = f2bf(di * v.x, di * v.y);
        st.y = f2bf(di * v.z, di * v.w);
        reinterpret_cast<uint2*>(g_bfA)[j] = st;
    }
}

// ---------------- counting-sort fill: atomic-free scatter -------------------
__global__ void fill_kernel(const int4* __restrict__ src4, const int4* __restrict__ dst4) {
    int i = blockIdx.x * blockDim.x + threadIdx.x;
    if (i < EDGE_VEC) {
        int4 s = src4[i];
        int4 d = dst4[i];
        int4 r = reinterpret_cast<const int4*>(g_rank)[i];
        int p0 = g_rowptr[d.x] + r.x;
        int p1 = g_rowptr[d.y] + r.y;
        int p2 = g_rowptr[d.z] + r.z;
        int p3 = g_rowptr[d.w] + r.w;
        g_srcsorted[p0] = s.x;
        g_srcsorted[p1] = s.y;
        g_srcsorted[p2] = s.z;
        g_srcsorted[p3] = s.w;
    }
}

// ---------------- aggregation: out[d] = di * (y[d] + sum y[s]) --------------
// one warp per node; lane owns 4 bf16 features (uint2)
__global__ void agg_kernel_bf(const unsigned* __restrict__ feat, unsigned* __restrict__ out) {
    int gtid = blockIdx.x * blockDim.x + threadIdx.x;
    int node = gtid >> 5;
    int lane = gtid & 31;
    if (node >= N_NODES) return;

    uint2 sv = reinterpret_cast<const uint2*>(feat + (size_t)node * (DIM / 2))[lane];
    float2 s0 = bf2f(sv.x), s1 = bf2f(sv.y);
    float4 acc = make_float4(s0.x, s0.y, s1.x, s1.y);

    int e0 = g_rowptr[node];
    int e1 = g_rowptr[node + 1];
    for (int eb = e0; eb < e1; eb += 32) {
        int nb = min(32, e1 - eb);
        int s = (lane < nb) ? g_srcsorted[eb + lane] : 0;
        for (int j = 0; j < nb; ++j) {
            int sj = __shfl_sync(0xffffffffu, s, j);
            uint2 d = reinterpret_cast<const uint2*>(feat + (size_t)sj * (DIM / 2))[lane];
            float2 f0 = bf2f(d.x), f1 = bf2f(d.y);
            acc.x += f0.x; acc.y += f0.y;
            acc.z += f1.x; acc.w += f1.y;
        }
    }
    float di = g_dinv[node];
    uint2 st;
    st.x = f2bf(di * acc.x, di * acc.y);
    st.y = f2bf(di * acc.z, di * acc.w);
    reinterpret_cast<uint2*>(out + (size_t)node * (DIM / 2))[lane] = st;
}

// ---------------- tensor-core GEMM: C = dinv ⊙ relu(A @ W1 + b1) (bf16) -----
// SCALE=1: multiply rows by dinv (layer-1 output feeds layer-2 agg as y1)
#define LDP 72
__global__ void gemm_mma_bf(const unsigned* __restrict__ A,
                            const float* __restrict__ bias,
                            unsigned* __restrict__ C, int M) {
    __shared__ __nv_bfloat16 As[128][LDP];
    __shared__ __nv_bfloat16 Ws[128][LDP];
    __shared__ float bs[DIM];

    int tid = threadIdx.x;
    int wid = tid >> 5, lane = tid & 31;
    int g = lane >> 2, t = lane & 3;
    int row0 = blockIdx.x * 128;
    int wr = wid * 16;

    if (tid < DIM) bs[tid] = bias[tid];

    float acc[16][4];
    #pragma unroll
    for (int nt = 0; nt < 16; ++nt)
        #pragma unroll
        for (int j = 0; j < 4; ++j) acc[nt][j] = 0.0f;

    const unsigned* Wt = g_W1t;

    #pragma unroll
    for (int kc = 0; kc < DIM; kc += 64) {
        #pragma unroll
        for (int i = 0; i < 4; ++i) {
            int id = i * 256 + tid;
            int r = id >> 3, p = id & 7;
            int grow = min(row0 + r, M - 1);
            uint4 v = *reinterpret_cast<const uint4*>(
                A + (size_t)grow * (DIM / 2) + kc / 2 + p * 4);
            *reinterpret_cast<uint4*>(&As[r][p * 8]) = v;
        }
        #pragma unroll
        for (int i = 0; i < 4; ++i) {
            int id = i * 256 + tid;
            int n = id >> 3, p = id & 7;
            uint4 v = *reinterpret_cast<const uint4*>(
                Wt + (size_t)n * (DIM / 2) + kc / 2 + p * 4);
            *reinterpret_cast<uint4*>(&Ws[n][p * 8]) = v;
        }
        __syncthreads();

        #pragma unroll
        for (int ks = 0; ks < 64; ks += 16) {
            unsigned a0 = *reinterpret_cast<const unsigned*>(&As[wr + g][ks + 2 * t]);
            unsigned a1 = *reinterpret_cast<const unsigned*>(&As[wr + g + 8][ks + 2 * t]);
            unsigned a2 = *reinterpret_cast<const unsigned*>(&As[wr + g][ks + 2 * t + 8]);
            unsigned a3 = *reinterpret_cast<const unsigned*>(&As[wr + g + 8][ks + 2 * t + 8]);
            #pragma unroll
            for (int nt = 0; nt < 16; ++nt) {
                unsigned b0 = *reinterpret_cast<const unsigned*>(&Ws[nt * 8 + g][ks + 2 * t]);
                unsigned b1 = *reinterpret_cast<const unsigned*>(&Ws[nt * 8 + g][ks + 2 * t + 8]);
                asm volatile(
                    "mma.sync.aligned.m16n8k16.row.col.f32.bf16.bf16.f32 "
                    "{%0,%1,%2,%3}, {%4,%5,%6,%7}, {%8,%9}, {%0,%1,%2,%3};\n"
                    : "+f"(acc[nt][0]), "+f"(acc[nt][1]), "+f"(acc[nt][2]), "+f"(acc[nt][3])
                    : "r"(a0), "r"(a1), "r"(a2), "r"(a3), "r"(b0), "r"(b1));
            }
        }
        __syncthreads();
    }

    int rA = row0 + wr + g;
    int rB = rA + 8;
    float sA = (rA < M) ? g_dinv[rA] : 0.0f;
    float sB = (rB < M) ? g_dinv[rB] : 0.0f;
    #pragma unroll
    for (int nt = 0; nt < 16; ++nt) {
        int col = nt * 8 + 2 * t;
        float bx = bs[col], by = bs[col + 1];
        if (rA < M) {
            float ox = fmaxf(acc[nt][0] + bx, 0.0f) * sA;
            float oy = fmaxf(acc[nt][1] + by, 0.0f) * sA;
            C[(size_t)rA * (DIM / 2) + col / 2] = f2bf(ox, oy);
        }
        if (rB < M) {
            float ox = fmaxf(acc[nt][2] + bx, 0.0f) * sB;
            float oy = fmaxf(acc[nt][3] + by, 0.0f) * sB;
            C[(size_t)rB * (DIM / 2) + col / 2] = f2bf(ox, oy);
        }
    }
}

// ---------------- fused mean-pool (sorted batch, bf16 in) + W2 GEMM + b2 -----
__global__ void pool_gemm_kernel(const uint2* __restrict__ feat2,
                                 const int* __restrict__ batch,
                                 const float* __restrict__ W2,
                                 const float* __restrict__ b2,
                                 float* __restrict__ out) {
    __shared__ float4 sa[4][32];
    __shared__ float p[DIM];
    int g = blockIdx.x;
    int tid = threadIdx.x;
    int q = tid >> 5, l = tid & 31;

    int lo = 0, hi = N_NODES;
    while (lo < hi) { int m = (lo + hi) >> 1; if (batch[m] < g) lo = m + 1; else hi = m; }
    int start = lo;
    hi = N_NODES;
    while (lo < hi) { int m = (lo + hi) >> 1; if (batch[m] < g + 1) lo = m + 1; else hi = m; }
    int end = lo;

    float4 acc = make_float4(0.f, 0.f, 0.f, 0.f);
    for (int n = start + q; n < end; n += 4) {
        uint2 d = feat2[(size_t)n * (DIM / 4) + l];
        float2 f0 = bf2f(d.x), f1 = bf2f(d.y);
        acc.x += f0.x; acc.y += f0.y; acc.z += f1.x; acc.w += f1.y;
    }
    sa[q][l] = acc;
    __syncthreads();
    if (q == 0) {
        float4 s = sa[0][l];
        #pragma unroll
        for (int r = 1; r < 4; ++r) {
            float4 v = sa[r][l];
            s.x += v.x; s.y += v.y; s.z += v.z; s.w += v.w;
        }
        float cnt = fmaxf((float)(end - start), 1.0f);
        p[l * 4 + 0] = s.x / cnt;
        p[l * 4 + 1] = s.y / cnt;
        p[l * 4 + 2] = s.z / cnt;
        p[l * 4 + 3] = s.w / cnt;
    }
    __syncthreads();

    int j = tid;
    float o = b2[j];
    #pragma unroll 8
    for (int k = 0; k < DIM; ++k)
        o += p[k] * W2[k * DIM + j];
    out[g * DIM + j] = o;
}

// ---------------- launch ----------------
extern "C" void kernel_launch(void* const* d_in, const int* in_sizes, int n_in,
                              void* d_out, int out_size) {
    const float* x     = (const float*)d_in[0];
    const int*   ei    = (const int*)d_in[1];
    const int*   batch = (const int*)d_in[2];
    const float* W1    = (const float*)d_in[3];
    const float* b1    = (const float*)d_in[4];
    const float* W2    = (const float*)d_in[5];
    const float* b2    = (const float*)d_in[6];
    float* out = (float*)d_out;

    const int4* src4 = (const int4*)ei;               // edge_index[0]
    const int4* dst4 = (const int4*)(ei + N_EDGES);   // edge_index[1]

    unsigned* bfA; cudaGetSymbolAddress((void**)&bfA, g_bfA);
    unsigned* bfB; cudaGetSymbolAddress((void**)&bfB, g_bfB);

    prep_kernel<<<PREP_W_BLOCKS + PREP_Z_BLOCKS, 256>>>(W1);
    hist_kernel<<<(EDGE_VEC + 255) / 256, 256>>>(dst4);
    scan_kernel<<<SCAN_BLOCKS, 1024>>>();
    convy_kernel<<<1280, 256>>>(x);                   // y0 = dinv .* x  (bf16)
    fill_kernel<<<(EDGE_VEC + 255) / 256, 256>>>(src4, dst4);

    int agg_blocks = (N_NODES * 32 + 255) / 256;
    // layer 1: agg(y0) -> bfB; y1 = dinv .* relu(bfB @ W1 + b1) -> bfA
    agg_kernel_bf<<<agg_blocks, 256>>>(bfA, bfB);
    gemm_mma_bf<<<(N_NODES + 127) / 128, 256>>>(bfB, b1, bfA, N_NODES);

    // layer 2: agg(y1) -> bfB; W2 deferred past pooling
    agg_kernel_bf<<<agg_blocks, 256>>>(bfA, bfB);

    // fused mean-pool + W2 GEMM + b2
    pool_gemm_kernel<<<N_GRAPHS, DIM>>>(
        reinterpret_cast<const uint2*>(bfB), batch, W2, b2, out);
}

// round 15
// speedup vs baseline: 1.1046x; 1.0065x over previous
#include <cuda_runtime.h>
#include <cuda_fp16.h>
#include <cuda_bf16.h>

// Problem constants
#define N_NODES   100000
#define N_EDGES   1600000
#define DIM       128
#define N_GRAPHS  1024
#define SCAN_BLOCKS 98          // ceil(100000/1024)
#define EDGE_VEC  (N_EDGES / 4) // 400000 int4 packets

// ---------------- scratch (__device__ globals: allocation-free) ----------------
__device__ unsigned g_bfA[(size_t)N_NODES * DIM / 2]; // 25.6 MB bf16x2: y0 / y1
__device__ unsigned g_bfB[(size_t)N_NODES * DIM / 2]; // 25.6 MB bf16x2: agg out
__device__ unsigned g_W1t[DIM * DIM / 2];             // W1^T in bf16: Wt[n][k]
__device__ int      g_srcsorted[N_EDGES];             // 6.4 MB: src per CSR slot
__device__ int      g_rank[N_EDGES];                  // 6.4 MB: edge rank in dst bucket
__device__ int      g_cnt[N_NODES];
__device__ float    g_dinv[N_NODES];
__device__ int      g_rowptr[N_NODES + 1];
__device__ unsigned long long g_scan_pack[SCAN_BLOCKS]; // (flag<<32)|value

// bf16x2 (packed u32) -> two fp32: pure ALU (SHF/LOP3)
__device__ __forceinline__ float2 bf2f(unsigned u) {
    float2 r;
    r.x = __uint_as_float(u << 16);
    r.y = __uint_as_float(u & 0xFFFF0000u);
    return r;
}
// two fp32 -> packed bf16x2 (F2FP, fixed-lat pipe)
__device__ __forceinline__ unsigned f2bf(float a, float b) {
    __nv_bfloat162 h = __floats2bfloat162_rn(a, b);
    return *reinterpret_cast<unsigned*>(&h);
}

__device__ __forceinline__ int wsum32(int v) {
    #pragma unroll
    for (int o = 16; o > 0; o >>= 1) v += __shfl_xor_sync(0xffffffffu, v, o);
    return v;
}

// ---------------- prep: W1 transpose->bf16 | zero cnt + scan flags ----------
#define PREP_W_BLOCKS 32
#define PREP_Z_BLOCKS 98
__global__ void prep_kernel(const float* __restrict__ W1) {
    int b = blockIdx.x;
    int tid = threadIdx.x;
    if (b < PREP_W_BLOCKS) {
        int i = b * 256 + tid;          // 0..8191
        int n = i >> 6;
        int k2 = (i & 63) * 2;
        float a = W1[(size_t)k2 * DIM + n];
        float c = W1[(size_t)(k2 + 1) * DIM + n];
        g_W1t[i] = f2bf(a, c);
    } else {
        int base = (b - PREP_W_BLOCKS) * 256 + tid;
        int stride = PREP_Z_BLOCKS * 256;
        for (int j = base; j < N_NODES; j += stride) g_cnt[j] = 0;
        if (base < SCAN_BLOCKS) g_scan_pack[base] = 0ULL;
    }
}

// ---------------- histogram + rank capture (counting-sort phase 1) -----------
__global__ void hist_kernel(const int4* __restrict__ dst4) {
    int i = blockIdx.x * blockDim.x + threadIdx.x;
    if (i < EDGE_VEC) {
        int4 d = dst4[i];
        int4 r;
        r.x = atomicAdd(&g_cnt[d.x], 1);
        r.y = atomicAdd(&g_cnt[d.y], 1);
        r.z = atomicAdd(&g_cnt[d.z], 1);
        r.w = atomicAdd(&g_cnt[d.w], 1);
        reinterpret_cast<int4*>(g_rank)[i] = r;
    }
}

// ---------------- fused scan + y0 convert -----------------------------------
// Phase 1: local scan + dinv, publish aggregate.
// Phase 2: stream-convert this block's 1024 rows of x into y0 = dinv .* x
//          (hides lookback latency of later blocks behind DRAM streaming).
// Phase 3: warp-0 decoupled lookback, write rowptr.
__global__ void scan_conv_kernel(const float4* __restrict__ x4) {
    __shared__ float s_dinv[1024];
    __shared__ int warp_sums[32];
    __shared__ int s_prefix;
    int tid = threadIdx.x, lane = tid & 31, wid = tid >> 5;
    int b = blockIdx.x;
    int i = b * 1024 + tid;
    int v = (i < N_NODES) ? g_cnt[i] : 0;
    float di = rsqrtf((float)(v + 1));
    if (i < N_NODES) g_dinv[i] = di;
    s_dinv[tid] = di;

    // local exclusive scan
    int x = v;
    #pragma unroll
    for (int o = 1; o < 32; o <<= 1) {
        int t = __shfl_up_sync(0xffffffffu, x, o);
        if (lane >= o) x += t;
    }
    if (lane == 31) warp_sums[wid] = x;
    __syncthreads();
    if (wid == 0) {
        int s = warp_sums[lane];
        #pragma unroll
        for (int o = 1; o < 32; o <<= 1) {
            int t = __shfl_up_sync(0xffffffffu, s, o);
            if (lane >= o) s += t;
        }
        warp_sums[lane] = s;
    }
    __syncthreads();
    int excl = (wid > 0 ? warp_sums[wid - 1] : 0) + x - v;
    int total = warp_sums[31];

    // publish aggregate early (so successors' lookbacks don't spin)
    if (tid == 0) {
        unsigned long long p = (b == 0)
            ? ((2ULL << 32) | (unsigned)total)
            : ((1ULL << 32) | (unsigned)total);
        atomicExch(&g_scan_pack[b], p);
    }

    // phase 2: convert this block's chunk (1024 rows x 32 float4 = 32768 packets)
    {
        const int TOTAL_P = N_NODES * (DIM / 4);
        size_t base = (size_t)b * 32768;
        #pragma unroll 4
        for (int it = 0; it < 32; ++it) {
            int off = it * 1024 + tid;
            size_t j = base + off;
            if (j < (size_t)TOTAL_P) {
                float d = s_dinv[off >> 5];
                float4 val = x4[j];
                uint2 st;
                st.x = f2bf(d * val.x, d * val.y);
                st.y = f2bf(d * val.z, d * val.w);
                reinterpret_cast<uint2*>(g_bfA)[j] = st;
            }
        }
    }

    // phase 3: decoupled lookback (warp 0)
    if (wid == 0) {
        int prefix = 0;
        if (b > 0) {
            int offset = 0;
            bool done = false;
            while (!done) {
                int my = b - 1 - offset - lane;
                int f = 2, val = 0;
                if (my >= 0) {
                    unsigned long long pv;
                    do {
                        pv = *((volatile unsigned long long*)&g_scan_pack[my]);
                        f = (int)(pv >> 32);
                    } while (f == 0);
                    val = (int)(pv & 0xffffffffULL);
                }
                unsigned m = __ballot_sync(0xffffffffu, f == 2);
                if (m == 0) {
                    prefix += wsum32(val);
                    offset += 32;
                } else {
                    int first = __ffs(m) - 1;
                    int c = (lane <= first) ? val : 0;
                    prefix += wsum32(c);
                    done = true;
                }
            }
        }
        if (lane == 0) {
            s_prefix = prefix;
            atomicExch(&g_scan_pack[b], (2ULL << 32) | (unsigned)(prefix + total));
        }
    }
    __syncthreads();
    int prefix = s_prefix;
    if (i < N_NODES) g_rowptr[i] = excl + prefix;
    if (b == 0 && tid == 0) g_rowptr[N_NODES] = N_EDGES;
}

// ---------------- counting-sort fill: atomic-free scatter -------------------
__global__ void fill_kernel(const int4* __restrict__ src4, const int4* __restrict__ dst4) {
    int i = blockIdx.x * blockDim.x + threadIdx.x;
    if (i < EDGE_VEC) {
        int4 s = src4[i];
        int4 d = dst4[i];
        int4 r = reinterpret_cast<const int4*>(g_rank)[i];
        int p0 = g_rowptr[d.x] + r.x;
        int p1 = g_rowptr[d.y] + r.y;
        int p2 = g_rowptr[d.z] + r.z;
        int p3 = g_rowptr[d.w] + r.w;
        g_srcsorted[p0] = s.x;
        g_srcsorted[p1] = s.y;
        g_srcsorted[p2] = s.z;
        g_srcsorted[p3] = s.w;
    }
}

// ---------------- aggregation: out[d] = di * (y[d] + sum y[s]) --------------
// one warp per node; lane owns 4 bf16 features (uint2)
__global__ void agg_kernel_bf(const unsigned* __restrict__ feat, unsigned* __restrict__ out) {
    int gtid = blockIdx.x * blockDim.x + threadIdx.x;
    int node = gtid >> 5;
    int lane = gtid & 31;
    if (node >= N_NODES) return;

    uint2 sv = reinterpret_cast<const uint2*>(feat + (size_t)node * (DIM / 2))[lane];
    float2 s0 = bf2f(sv.x), s1 = bf2f(sv.y);
    float4 acc = make_float4(s0.x, s0.y, s1.x, s1.y);

    int e0 = g_rowptr[node];
    int e1 = g_rowptr[node + 1];
    for (int eb = e0; eb < e1; eb += 32) {
        int nb = min(32, e1 - eb);
        int s = (lane < nb) ? g_srcsorted[eb + lane] : 0;
        for (int j = 0; j < nb; ++j) {
            int sj = __shfl_sync(0xffffffffu, s, j);
            uint2 d = reinterpret_cast<const uint2*>(feat + (size_t)sj * (DIM / 2))[lane];
            float2 f0 = bf2f(d.x), f1 = bf2f(d.y);
            acc.x += f0.x; acc.y += f0.y;
            acc.z += f1.x; acc.w += f1.y;
        }
    }
    float di = g_dinv[node];
    uint2 st;
    st.x = f2bf(di * acc.x, di * acc.y);
    st.y = f2bf(di * acc.z, di * acc.w);
    reinterpret_cast<uint2*>(out + (size_t)node * (DIM / 2))[lane] = st;
}

// ---------------- tensor-core GEMM: C = dinv ⊙ relu(A @ W1 + b1) (bf16) -----
#define LDP 72
__global__ void gemm_mma_bf(const unsigned* __restrict__ A,
                            const float* __restrict__ bias,
                            unsigned* __restrict__ C, int M) {
    __shared__ __nv_bfloat16 As[128][LDP];
    __shared__ __nv_bfloat16 Ws[128][LDP];
    __shared__ float bs[DIM];

    int tid = threadIdx.x;
    int wid = tid >> 5, lane = tid & 31;
    int g = lane >> 2, t = lane & 3;
    int row0 = blockIdx.x * 128;
    int wr = wid * 16;

    if (tid < DIM) bs[tid] = bias[tid];

    float acc[16][4];
    #pragma unroll
    for (int nt = 0; nt < 16; ++nt)
        #pragma unroll
        for (int j = 0; j < 4; ++j) acc[nt][j] = 0.0f;

    const unsigned* Wt = g_W1t;

    #pragma unroll
    for (int kc = 0; kc < DIM; kc += 64) {
        #pragma unroll
        for (int i = 0; i < 4; ++i) {
            int id = i * 256 + tid;
            int r = id >> 3, p = id & 7;
            int grow = min(row0 + r, M - 1);
            uint4 v = *reinterpret_cast<const uint4*>(
                A + (size_t)grow * (DIM / 2) + kc / 2 + p * 4);
            *reinterpret_cast<uint4*>(&As[r][p * 8]) = v;
        }
        #pragma unroll
        for (int i = 0; i < 4; ++i) {
            int id = i * 256 + tid;
            int n = id >> 3, p = id & 7;
            uint4 v = *reinterpret_cast<const uint4*>(
                Wt + (size_t)n * (DIM / 2) + kc / 2 + p * 4);
            *reinterpret_cast<uint4*>(&Ws[n][p * 8]) = v;
        }
        __syncthreads();

        #pragma unroll
        for (int ks = 0; ks < 64; ks += 16) {
            unsigned a0 = *reinterpret_cast<const unsigned*>(&As[wr + g][ks + 2 * t]);
            unsigned a1 = *reinterpret_cast<const unsigned*>(&As[wr + g + 8][ks + 2 * t]);
            unsigned a2 = *reinterpret_cast<const unsigned*>(&As[wr + g][ks + 2 * t + 8]);
            unsigned a3 = *reinterpret_cast<const unsigned*>(&As[wr + g + 8][ks + 2 * t + 8]);
            #pragma unroll
            for (int nt = 0; nt < 16; ++nt) {
                unsigned b0 = *reinterpret_cast<const unsigned*>(&Ws[nt * 8 + g][ks + 2 * t]);
                unsigned b1 = *reinterpret_cast<const unsigned*>(&Ws[nt * 8 + g][ks + 2 * t + 8]);
                asm volatile(
                    "mma.sync.aligned.m16n8k16.row.col.f32.bf16.bf16.f32 "
                    "{%0,%1,%2,%3}, {%4,%5,%6,%7}, {%8,%9}, {%0,%1,%2,%3};\n"
                    : "+f"(acc[nt][0]), "+f"(acc[nt][1]), "+f"(acc[nt][2]), "+f"(acc[nt][3])
                    : "r"(a0), "r"(a1), "r"(a2), "r"(a3), "r"(b0), "r"(b1));
            }
        }
        __syncthreads();
    }

    int rA = row0 + wr + g;
    int rB = rA + 8;
    float sA = (rA < M) ? g_dinv[rA] : 0.0f;
    float sB = (rB < M) ? g_dinv[rB] : 0.0f;
    #pragma unroll
    for (int nt = 0; nt < 16; ++nt) {
        int col = nt * 8 + 2 * t;
        float bx = bs[col], by = bs[col + 1];
        if (rA < M) {
            float ox = fmaxf(acc[nt][0] + bx, 0.0f) * sA;
            float oy = fmaxf(acc[nt][1] + by, 0.0f) * sA;
            C[(size_t)rA * (DIM / 2) + col / 2] = f2bf(ox, oy);
        }
        if (rB < M) {
            float ox = fmaxf(acc[nt][2] + bx, 0.0f) * sB;
            float oy = fmaxf(acc[nt][3] + by, 0.0f) * sB;
            C[(size_t)rB * (DIM / 2) + col / 2] = f2bf(ox, oy);
        }
    }
}

// ---------------- fused mean-pool (sorted batch, bf16 in) + W2 GEMM + b2 -----
// 256 thr: q=tid>>5 (8 rows in flight), l=tid&31 owns 4 features
__global__ void pool_gemm_kernel(const uint2* __restrict__ feat2,
                                 const int* __restrict__ batch,
                                 const float* __restrict__ W2,
                                 const float* __restrict__ b2,
                                 float* __restrict__ out) {
    __shared__ float4 sa[8][32];
    __shared__ float p[DIM];
    int g = blockIdx.x;
    int tid = threadIdx.x;
    int q = tid >> 5, l = tid & 31;

    int lo = 0, hi = N_NODES;
    while (lo < hi) { int m = (lo + hi) >> 1; if (batch[m] < g) lo = m + 1; else hi = m; }
    int start = lo;
    hi = N_NODES;
    while (lo < hi) { int m = (lo + hi) >> 1; if (batch[m] < g + 1) lo = m + 1; else hi = m; }
    int end = lo;

    float4 acc = make_float4(0.f, 0.f, 0.f, 0.f);
    for (int n = start + q; n < end; n += 8) {
        uint2 d = feat2[(size_t)n * (DIM / 4) + l];
        float2 f0 = bf2f(d.x), f1 = bf2f(d.y);
        acc.x += f0.x; acc.y += f0.y; acc.z += f1.x; acc.w += f1.y;
    }
    sa[q][l] = acc;
    __syncthreads();
    if (q == 0) {
        float4 s = sa[0][l];
        #pragma unroll
        for (int r = 1; r < 8; ++r) {
            float4 v = sa[r][l];
            s.x += v.x; s.y += v.y; s.z += v.z; s.w += v.w;
        }
        float cnt = fmaxf((float)(end - start), 1.0f);
        p[l * 4 + 0] = s.x / cnt;
        p[l * 4 + 1] = s.y / cnt;
        p[l * 4 + 2] = s.z / cnt;
        p[l * 4 + 3] = s.w / cnt;
    }
    __syncthreads();

    if (tid < DIM) {
        int j = tid;
        float o = b2[j];
        #pragma unroll 8
        for (int k = 0; k < DIM; ++k)
            o += p[k] * W2[k * DIM + j];
        out[g * DIM + j] = o;
    }
}

// ---------------- launch ----------------
extern "C" void kernel_launch(void* const* d_in, const int* in_sizes, int n_in,
                              void* d_out, int out_size) {
    const float* x     = (const float*)d_in[0];
    const int*   ei    = (const int*)d_in[1];
    const int*   batch = (const int*)d_in[2];
    const float* W1    = (const float*)d_in[3];
    const float* b1    = (const float*)d_in[4];
    const float* W2    = (const float*)d_in[5];
    const float* b2    = (const float*)d_in[6];
    float* out = (float*)d_out;

    const int4* src4 = (const int4*)ei;               // edge_index[0]
    const int4* dst4 = (const int4*)(ei + N_EDGES);   // edge_index[1]

    unsigned* bfA; cudaGetSymbolAddress((void**)&bfA, g_bfA);
    unsigned* bfB; cudaGetSymbolAddress((void**)&bfB, g_bfB);

    prep_kernel<<<PREP_W_BLOCKS + PREP_Z_BLOCKS, 256>>>(W1);
    hist_kernel<<<(EDGE_VEC + 255) / 256, 256>>>(dst4);
    scan_conv_kernel<<<SCAN_BLOCKS, 1024>>>((const float4*)x);  // scan + y0 = dinv.*x
    fill_kernel<<<(EDGE_VEC + 255) / 256, 256>>>(src4, dst4);

    int agg_blocks = (N_NODES * 32 + 255) / 256;
    // layer 1: agg(y0) -> bfB; y1 = dinv .* relu(bfB @ W1 + b1) -> bfA
    agg_kernel_bf<<<agg_blocks, 256>>>(bfA, bfB);
    gemm_mma_bf<<<(N_NODES + 127) / 128, 256>>>(bfB, b1, bfA, N_NODES);

    // layer 2: agg(y1) -> bfB; W2 deferred past pooling
    agg_kernel_bf<<<agg_blocks, 256>>>(bfA, bfB);

    // fused mean-pool + W2 GEMM + b2
    pool_gemm_kernel<<<N_GRAPHS, 256>>>(
        reinterpret_cast<const uint2*>(bfB), batch, W2, b2, out);
}